// round 7
// baseline (speedup 1.0000x reference)
#include <cuda_runtime.h>
#include <math.h>

#define NCTA 128
#define NTHR 256
#define CLSZ 16     // CTAs per cluster
#define Bb 256      // batch
#define Ss 512      // seq len
#define Ii 256      // input dim
#define Hh 512      // hidden dim
#define BBd 256     // backbone dim
#define Oo 128      // out dim

typedef unsigned long long u64;

// ===================== cluster kernel shared-mem layout =====================
#define P1   772    // stage1 weight pitch (768 + 4), 16B aligned
#define PB   260    // backbone weight pitch (256 + 4), 16B aligned
#define OFF_W1  0
#define SZ_W1   (16 * P1)              // 12352
#define OFF_WB  (OFF_W1 + SZ_W1)
#define SZ_WB   (48 * PB)              // 12480
#define OFF_WH  (OFF_WB + SZ_WB)       // 24832
#define SZ_WH   (128 * 256)            // 32768 (swizzled, unpadded)
#define SMEM_CL_FLOATS (OFF_WH + SZ_WH)    // 57600
#define SMEM_CL_BYTES  (SMEM_CL_FLOATS * 4) // 230400 <= 232448

// ===================== fallback kernel shared-mem layout ====================
#define FB_P1   772
#define FB_PB   260
#define FB_OFF_W1  0
#define FB_SZ_W1   (16 * FB_P1)
#define FB_OFF_WB  (FB_OFF_W1 + FB_SZ_W1)
#define FB_SZ_WB   (48 * FB_PB)
#define FB_OFF_WH  (FB_OFF_WB + FB_SZ_WB)
#define FB_SZ_WH   (64 * FB_PB)
#define FB_OFF_ACT (FB_OFF_WH + FB_SZ_WH)
#define FB_SZ_ACTBUF 4352
#define FB_SZ_ACT  (2 * FB_SZ_ACTBUF)
#define FB_SMEM_FLOATS (FB_OFF_ACT + FB_SZ_ACT)
#define FB_SMEM_BYTES  (FB_SMEM_FLOATS * 4)   // 200704

// ---------------- device scratch (static globals: allocation-free) ----------
__device__ float g_h[Bb * Hh];       // hidden state  [256][512]
__device__ float g_zA[Bb * BBd];     // backbone ping  [256][256]
__device__ float g_zB[Bb * BBd];     // backbone pong  [256][256]
__device__ int   g_abort = 0;        // watchdog (fallback only)

struct __align__(128) Bar { unsigned count; unsigned gen; unsigned pad[30]; };
__device__ Bar g_bar16[8];
__device__ Bar g_bar32[4];

// ---------------- packed f32x2 FMA helpers ---------------------------------
__device__ __forceinline__ u64 ffma2(u64 a, u64 b, u64 c) {
    u64 d;
    asm("fma.rn.f32x2 %0, %1, %2, %3;" : "=l"(d) : "l"(a), "l"(b), "l"(c));
    return d;
}
__device__ __forceinline__ float sum2(u64 v) {
    union { u64 u; float2 f; } cv; cv.u = v;
    return cv.f.x + cv.f.y;
}

// Cluster barrier with correct global-memory producer->consumer ordering.
// __threadfence() (fence.sc.gpu, scope >= cluster) emits CCTL.IVALL: the
// release side pushes/orders stores, the acquire side invalidates this SM's
// L1D so re-reads of the same g_z*/g_h addresses can't hit stale lines.
// One thread's CCTL.IVALL covers the whole SM (1 CTA/SM here).
__device__ __forceinline__ void cluster_sync_hw() {
    __syncthreads();                       // all warps' stores issued
    if (threadIdx.x == 0) __threadfence(); // release + L1D flush
    __syncthreads();
    asm volatile("barrier.cluster.arrive.aligned;" ::: "memory");
    asm volatile("barrier.cluster.wait.aligned;"   ::: "memory");
    if (threadIdx.x == 0) __threadfence(); // acquire: invalidate stale L1D
    __syncthreads();
}

// MAC over NQ 16-byte k-units: 2 activation rows (global) x 1 weight col (smem)
template<int NQ>
__device__ __forceinline__ void mac2row(const float* a0g, const float* a1g,
                                        const float* ws,
                                        u64& p0a, u64& p0b, u64& p1a, u64& p1b) {
    const ulonglong2* a0 = (const ulonglong2*)a0g;
    const ulonglong2* a1 = (const ulonglong2*)a1g;
    const ulonglong2* w  = (const ulonglong2*)ws;
#pragma unroll 16
    for (int q = 0; q < NQ; q++) {
        ulonglong2 wv = w[q];
        ulonglong2 x0 = a0[q];
        ulonglong2 x1 = a1[q];
        p0a = ffma2(x0.x, wv.x, p0a);
        p0b = ffma2(x0.y, wv.y, p0b);
        p1a = ffma2(x1.x, wv.x, p1a);
        p1b = ffma2(x1.y, wv.y, p1b);
    }
}

// ============================================================================
//                 CLUSTER KERNEL (16-CTA clusters, hw barriers)
// ============================================================================
__global__ void __launch_bounds__(NTHR, 1)
lnn_cluster_kernel(const float* __restrict__ x,     const float* __restrict__ ts,
                   const float* __restrict__ Wb0,   const float* __restrict__ bb0,
                   const float* __restrict__ Wbs,   const float* __restrict__ bbs,
                   const float* __restrict__ W_ff1, const float* __restrict__ b_ff1,
                   const float* __restrict__ W_ff2, const float* __restrict__ b_ff2,
                   const float* __restrict__ W_ta,  const float* __restrict__ b_ta,
                   const float* __restrict__ W_tb,  const float* __restrict__ b_tb,
                   const float* __restrict__ W_out, const float* __restrict__ b_out,
                   float* __restrict__ out) {
    extern __shared__ float smf[];
    const int tid = threadIdx.x;
    const int g   = blockIdx.x;
    const int c   = g >> 4;            // cluster id 0..7  (32 batch rows each)
    const int r   = g & 15;            // rank in cluster 0..15
    const int n   = tid & 15;          // stage1/backbone: 32 rows x 16 cols
    const int mg  = tid >> 4;          // 0..15 (2 rows each)
    const int nh  = tid & 31;          // heads: 32 rows x 32 cols
    const int mgh = tid >> 5;          // 0..7 (4 rows each)

    // ---- one-time weight loads into SMEM ----
    for (int e = tid; e < 16 * 768; e += NTHR) {
        int nn = e / 768, k = e % 768;
        smf[OFF_W1 + nn * P1 + k] = Wb0[k * BBd + r * 16 + nn];
    }
    for (int e = tid; e < 3 * 16 * 256; e += NTHR) {
        int l = e / (16 * 256);
        int rr = e % (16 * 256);
        int nn = rr / 256, k = rr % 256;
        smf[OFF_WB + (l * 16 + nn) * PB + k] = Wbs[(l * BBd + k) * BBd + r * 16 + nn];
    }
    // heads: 128 rows (mat*32 + jj) x 256 k, XOR-swizzled 16B units, no padding
    for (int e = tid; e < 128 * 256; e += NTHR) {
        int row = e / 256, k = e % 256;
        int mat = row >> 5, jj = row & 31;
        const float* Wsrc = (mat == 0) ? W_ff1 : (mat == 1) ? W_ff2 : (mat == 2) ? W_ta : W_tb;
        int phys = OFF_WH + row * 256 + ((((k >> 2) ^ (row & 7)) << 2) | (k & 3));
        smf[phys] = Wsrc[k * Hh + r * 32 + jj];
    }
    // biases
    float bz0   = bb0[r * 16 + n];
    float bb_l0 = bbs[0 * BBd + r * 16 + n];
    float bb_l1 = bbs[1 * BBd + r * 16 + n];
    float bb_l2 = bbs[2 * BBd + r * 16 + n];
    float bf1   = b_ff1[r * 32 + nh];
    float bf2   = b_ff2[r * 32 + nh];
    float bta   = b_ta [r * 32 + nh];
    float btb   = b_tb [r * 32 + nh];

    // zero this cluster's h rows (each CTA a 1024-float stripe)
    {
        float* hbase = g_h + (size_t)c * 32 * Hh + r * 1024;
        for (int e = tid; e < 1024; e += NTHR) hbase[e] = 0.0f;
    }
    cluster_sync_hw();

    const int r2 = c * 32 + mg * 2;    // stage1/backbone row pair
    const int r4 = c * 32 + mgh * 4;   // heads row quad
    const int jS = r * 16 + n;         // stage1/backbone output col
    const int jH = r * 32 + nh;        // heads output col
    const int swz = nh & 7;

    for (int t = 0; t < Ss; t++) {
        // ===== stage 1: z0 = tanh([x_t,h] @ Wb0 + bb0) =====
        {
            u64 p0a = 0, p0b = 0, p1a = 0, p1b = 0;
            const float* x0 = x + ((size_t)r2 * Ss + t) * Ii;
            const float* x1 = x0 + (size_t)Ss * Ii;
            mac2row<64>(x0, x1, smf + OFF_W1 + n * P1, p0a, p0b, p1a, p1b);
            const float* h0 = g_h + (size_t)r2 * Hh;
            mac2row<128>(h0, h0 + Hh, smf + OFF_W1 + n * P1 + 256, p0a, p0b, p1a, p1b);
            float acc0 = sum2(p0a) + sum2(p0b);
            float acc1 = sum2(p1a) + sum2(p1b);
            g_zA[r2 * BBd + jS]       = tanhf(acc0 + bz0);
            g_zA[(r2 + 1) * BBd + jS] = tanhf(acc1 + bz0);
        }
        cluster_sync_hw();

        // ===== backbone: 3x z = tanh(z @ Wbs[l] + bbs[l]) =====
#pragma unroll
        for (int l = 0; l < 3; l++) {
            const float* zin = (l == 1) ? g_zB : g_zA;
            float*       zot = (l == 1) ? g_zA : g_zB;
            u64 p0a = 0, p0b = 0, p1a = 0, p1b = 0;
            const float* z0 = zin + r2 * BBd;
            mac2row<64>(z0, z0 + BBd, smf + OFF_WB + (l * 16 + n) * PB,
                        p0a, p0b, p1a, p1b);
            float bl = (l == 0) ? bb_l0 : (l == 1) ? bb_l1 : bb_l2;
            float acc0 = sum2(p0a) + sum2(p0b);
            float acc1 = sum2(p1a) + sum2(p1b);
            zot[r2 * BBd + jS]       = tanhf(acc0 + bl);
            zot[(r2 + 1) * BBd + jS] = tanhf(acc1 + bl);
            cluster_sync_hw();
        }

        // ===== heads: ff1/ff2/ta/tb + gate -> new h =====
        {
            u64 acc[4][4];
#pragma unroll
            for (int i = 0; i < 4; i++)
#pragma unroll
                for (int hh = 0; hh < 4; hh++) acc[i][hh] = 0;

            const ulonglong2* a0 = (const ulonglong2*)(g_zB + (r4 + 0) * BBd);
            const ulonglong2* a1 = (const ulonglong2*)(g_zB + (r4 + 1) * BBd);
            const ulonglong2* a2 = (const ulonglong2*)(g_zB + (r4 + 2) * BBd);
            const ulonglong2* a3 = (const ulonglong2*)(g_zB + (r4 + 3) * BBd);
            const ulonglong2* wb = (const ulonglong2*)(smf + OFF_WH);
            const int w0i = (0 * 32 + nh) * 64;
            const int w1i = (1 * 32 + nh) * 64;
            const int w2i = (2 * 32 + nh) * 64;
            const int w3i = (3 * 32 + nh) * 64;
#pragma unroll 8
            for (int q = 0; q < 64; q++) {
                int qs = q ^ swz;
                ulonglong2 wv0 = wb[w0i + qs], wv1 = wb[w1i + qs];
                ulonglong2 wv2 = wb[w2i + qs], wv3 = wb[w3i + qs];
                ulonglong2 av;
                av = a0[q];
                acc[0][0] = ffma2(av.x, wv0.x, acc[0][0]); acc[0][0] = ffma2(av.y, wv0.y, acc[0][0]);
                acc[0][1] = ffma2(av.x, wv1.x, acc[0][1]); acc[0][1] = ffma2(av.y, wv1.y, acc[0][1]);
                acc[0][2] = ffma2(av.x, wv2.x, acc[0][2]); acc[0][2] = ffma2(av.y, wv2.y, acc[0][2]);
                acc[0][3] = ffma2(av.x, wv3.x, acc[0][3]); acc[0][3] = ffma2(av.y, wv3.y, acc[0][3]);
                av = a1[q];
                acc[1][0] = ffma2(av.x, wv0.x, acc[1][0]); acc[1][0] = ffma2(av.y, wv0.y, acc[1][0]);
                acc[1][1] = ffma2(av.x, wv1.x, acc[1][1]); acc[1][1] = ffma2(av.y, wv1.y, acc[1][1]);
                acc[1][2] = ffma2(av.x, wv2.x, acc[1][2]); acc[1][2] = ffma2(av.y, wv2.y, acc[1][2]);
                acc[1][3] = ffma2(av.x, wv3.x, acc[1][3]); acc[1][3] = ffma2(av.y, wv3.y, acc[1][3]);
                av = a2[q];
                acc[2][0] = ffma2(av.x, wv0.x, acc[2][0]); acc[2][0] = ffma2(av.y, wv0.y, acc[2][0]);
                acc[2][1] = ffma2(av.x, wv1.x, acc[2][1]); acc[2][1] = ffma2(av.y, wv1.y, acc[2][1]);
                acc[2][2] = ffma2(av.x, wv2.x, acc[2][2]); acc[2][2] = ffma2(av.y, wv2.y, acc[2][2]);
                acc[2][3] = ffma2(av.x, wv3.x, acc[2][3]); acc[2][3] = ffma2(av.y, wv3.y, acc[2][3]);
                av = a3[q];
                acc[3][0] = ffma2(av.x, wv0.x, acc[3][0]); acc[3][0] = ffma2(av.y, wv0.y, acc[3][0]);
                acc[3][1] = ffma2(av.x, wv1.x, acc[3][1]); acc[3][1] = ffma2(av.y, wv1.y, acc[3][1]);
                acc[3][2] = ffma2(av.x, wv2.x, acc[3][2]); acc[3][2] = ffma2(av.y, wv2.y, acc[3][2]);
                acc[3][3] = ffma2(av.x, wv3.x, acc[3][3]); acc[3][3] = ffma2(av.y, wv3.y, acc[3][3]);
            }
#pragma unroll
            for (int i = 0; i < 4; i++) {
                int b = r4 + i;
                float tst = ts[(size_t)b * Ss + t];
                float f1  = tanhf(sum2(acc[i][0]) + bf1);
                float f2  = tanhf(sum2(acc[i][1]) + bf2);
                float ta_ = sum2(acc[i][2]) + bta;
                float tb_ = sum2(acc[i][3]) + btb;
                float ti  = 1.0f / (1.0f + expf(-(ta_ * tst + tb_)));
                g_h[b * Hh + jH] = f1 + ti * (f2 - f1);
            }
        }
        cluster_sync_hw();
    }

    // ===== final: out = h_last @ W_out + b_out (cluster-local rows) =====
    {
        int m   = c * 32 + r * 2 + (tid >> 7);
        int col = tid & 127;
        float acc = b_out[col];
        const float* hr = g_h + (size_t)m * Hh;
#pragma unroll 8
        for (int k = 0; k < Hh; k++) acc += hr[k] * W_out[k * Oo + col];
        out[m * Oo + col] = acc;
    }
}

// ============================================================================
//          FALLBACK KERNEL (R4: software group barriers + cp.async)
// ============================================================================
__device__ __forceinline__ void group_barrier(Bar* b, unsigned nctas) {
    __syncthreads();
    if (threadIdx.x == 0) {
        if (!*(volatile int*)&g_abort) {
            __threadfence();
            volatile unsigned* vgen = (volatile unsigned*)&b->gen;
            unsigned gen = *vgen;
            unsigned rank = atomicAdd(&b->count, 1);
            if (rank == nctas - 1) {
                atomicExch(&b->count, 0);
                __threadfence();
                atomicAdd((unsigned*)&b->gen, 1);
            } else {
                long long t0 = clock64();
                while (*vgen == gen) {
                    __nanosleep(32);
                    if (*(volatile int*)&g_abort) break;
                    if (clock64() - t0 > 2000000000LL) { atomicExch(&g_abort, 1); break; }
                }
            }
            __threadfence();
        }
    }
    __syncthreads();
}
__device__ __forceinline__ void cp16(float* sdst, const float* gsrc) {
    unsigned saddr = (unsigned)__cvta_generic_to_shared(sdst);
    asm volatile("cp.async.cg.shared.global [%0], [%1], 16;" :: "r"(saddr), "l"(gsrc));
}
__device__ __forceinline__ void cp_commit() { asm volatile("cp.async.commit_group;"); }
__device__ __forceinline__ void cp_wait0()  { asm volatile("cp.async.wait_group 0;"); }
__device__ __forceinline__ void cp_wait1()  { asm volatile("cp.async.wait_group 1;"); }

#define FB_PA1  132
#define FB_PAH  68
__device__ __forceinline__ void fb_load_rows32(float* sdst, const float* gbase, int gstride) {
    int tid = threadIdx.x;
#pragma unroll
    for (int i = 0; i < 4; i++) {
        int e = tid + i * 256;
        int rr = e >> 5, v = e & 31;
        cp16(sdst + rr * FB_PA1 + v * 4, gbase + (size_t)rr * gstride + v * 4);
    }
}
__device__ __forceinline__ void fb_load_rows64(float* sdst, const float* gbase, int gstride) {
    int tid = threadIdx.x;
#pragma unroll
    for (int i = 0; i < 4; i++) {
        int e = tid + i * 256;
        int rr = e >> 4, v = e & 15;
        cp16(sdst + rr * FB_PAH + v * 4, gbase + (size_t)rr * gstride + v * 4);
    }
}
__device__ __forceinline__ void fb_mac32x16(const float* sA, const float* wrow,
                                            u64& p0a, u64& p0b, u64& p1a, u64& p1b, int mg) {
    const ulonglong2* a0 = (const ulonglong2*)(sA + (mg * 2) * FB_PA1);
    const ulonglong2* a1 = (const ulonglong2*)(sA + (mg * 2 + 1) * FB_PA1);
    const ulonglong2* w4 = (const ulonglong2*)wrow;
#pragma unroll
    for (int q = 0; q < 32; q++) {
        ulonglong2 w  = w4[q];
        ulonglong2 x0 = a0[q];
        ulonglong2 x1 = a1[q];
        p0a = ffma2(x0.x, w.x, p0a);
        p0b = ffma2(x0.y, w.y, p0b);
        p1a = ffma2(x1.x, w.x, p1a);
        p1b = ffma2(x1.y, w.y, p1b);
    }
}
__device__ __forceinline__ void fb_mac_heads(const float* sA, const float* wbase,
                                             int mg, int ng, u64 acc[4][4]) {
    const ulonglong2* a0 = (const ulonglong2*)(sA + (mg * 4 + 0) * FB_PAH);
    const ulonglong2* a1 = (const ulonglong2*)(sA + (mg * 4 + 1) * FB_PAH);
    const ulonglong2* a2 = (const ulonglong2*)(sA + (mg * 4 + 2) * FB_PAH);
    const ulonglong2* a3 = (const ulonglong2*)(sA + (mg * 4 + 3) * FB_PAH);
    const ulonglong2* w0 = (const ulonglong2*)(wbase + (0 * 16 + ng) * FB_PB);
    const ulonglong2* w1 = (const ulonglong2*)(wbase + (1 * 16 + ng) * FB_PB);
    const ulonglong2* w2 = (const ulonglong2*)(wbase + (2 * 16 + ng) * FB_PB);
    const ulonglong2* w3 = (const ulonglong2*)(wbase + (3 * 16 + ng) * FB_PB);
#pragma unroll
    for (int q = 0; q < 16; q++) {
        ulonglong2 wv0 = w0[q], wv1 = w1[q], wv2 = w2[q], wv3 = w3[q];
        ulonglong2 av;
        av = a0[q];
        acc[0][0] = ffma2(av.x, wv0.x, acc[0][0]); acc[0][0] = ffma2(av.y, wv0.y, acc[0][0]);
        acc[0][1] = ffma2(av.x, wv1.x, acc[0][1]); acc[0][1] = ffma2(av.y, wv1.y, acc[0][1]);
        acc[0][2] = ffma2(av.x, wv2.x, acc[0][2]); acc[0][2] = ffma2(av.y, wv2.y, acc[0][2]);
        acc[0][3] = ffma2(av.x, wv3.x, acc[0][3]); acc[0][3] = ffma2(av.y, wv3.y, acc[0][3]);
        av = a1[q];
        acc[1][0] = ffma2(av.x, wv0.x, acc[1][0]); acc[1][0] = ffma2(av.y, wv0.y, acc[1][0]);
        acc[1][1] = ffma2(av.x, wv1.x, acc[1][1]); acc[1][1] = ffma2(av.y, wv1.y, acc[1][1]);
        acc[1][2] = ffma2(av.x, wv2.x, acc[1][2]); acc[1][2] = ffma2(av.y, wv2.y, acc[1][2]);
        acc[1][3] = ffma2(av.x, wv3.x, acc[1][3]); acc[1][3] = ffma2(av.y, wv3.y, acc[1][3]);
        av = a2[q];
        acc[2][0] = ffma2(av.x, wv0.x, acc[2][0]); acc[2][0] = ffma2(av.y, wv0.y, acc[2][0]);
        acc[2][1] = ffma2(av.x, wv1.x, acc[2][1]); acc[2][1] = ffma2(av.y, wv1.y, acc[2][1]);
        acc[2][2] = ffma2(av.x, wv2.x, acc[2][2]); acc[2][2] = ffma2(av.y, wv2.y, acc[2][2]);
        acc[2][3] = ffma2(av.x, wv3.x, acc[2][3]); acc[2][3] = ffma2(av.y, wv3.y, acc[2][3]);
        av = a3[q];
        acc[3][0] = ffma2(av.x, wv0.x, acc[3][0]); acc[3][0] = ffma2(av.y, wv0.y, acc[3][0]);
        acc[3][1] = ffma2(av.x, wv1.x, acc[3][1]); acc[3][1] = ffma2(av.y, wv1.y, acc[3][1]);
        acc[3][2] = ffma2(av.x, wv2.x, acc[3][2]); acc[3][2] = ffma2(av.y, wv2.y, acc[3][2]);
        acc[3][3] = ffma2(av.x, wv3.x, acc[3][3]); acc[3][3] = ffma2(av.y, wv3.y, acc[3][3]);
    }
}

__global__ void __launch_bounds__(NTHR, 1)
lnn_fallback_kernel(const float* __restrict__ x,     const float* __restrict__ ts,
                    const float* __restrict__ Wb0,   const float* __restrict__ bb0,
                    const float* __restrict__ Wbs,   const float* __restrict__ bbs,
                    const float* __restrict__ W_ff1, const float* __restrict__ b_ff1,
                    const float* __restrict__ W_ff2, const float* __restrict__ b_ff2,
                    const float* __restrict__ W_ta,  const float* __restrict__ b_ta,
                    const float* __restrict__ W_tb,  const float* __restrict__ b_tb,
                    const float* __restrict__ W_out, const float* __restrict__ b_out,
                    float* __restrict__ out) {
    extern __shared__ float smf[];
    const int tid = threadIdx.x;
    const int g   = blockIdx.x;
    const int n   = tid & 15;
    const int mg  = tid >> 4;
    const int m1  = g >> 4;
    const int n1  = g & 15;
    const int mh  = g >> 5;
    const int jh  = g & 31;

    Bar* barS = &g_bar16[m1];
    Bar* barH = &g_bar32[mh];

    if (tid == 0) *(volatile int*)&g_abort = 0;

    for (int e = tid; e < 16 * 768; e += NTHR) {
        int nn = e / 768, k = e % 768;
        smf[FB_OFF_W1 + nn * FB_P1 + k] = Wb0[k * BBd + n1 * 16 + nn];
    }
    for (int e = tid; e < 3 * 16 * 256; e += NTHR) {
        int l = e / (16 * 256);
        int rr = e % (16 * 256);
        int nn = rr / 256, k = rr % 256;
        smf[FB_OFF_WB + (l * 16 + nn) * FB_PB + k] = Wbs[(l * BBd + k) * BBd + n1 * 16 + nn];
    }
    for (int e = tid; e < 64 * 256; e += NTHR) {
        int rr = e / 256, k = e % 256;
        int hh = rr / 16, ng = rr % 16;
        const float* Wsrc = (hh == 0) ? W_ff1 : (hh == 1) ? W_ff2 : (hh == 2) ? W_ta : W_tb;
        smf[FB_OFF_WH + rr * FB_PB + k] = Wsrc[k * Hh + jh * 16 + ng];
    }
    float bz0   = bb0[n1 * 16 + n];
    float bb_l0 = bbs[0 * BBd + n1 * 16 + n];
    float bb_l1 = bbs[1 * BBd + n1 * 16 + n];
    float bb_l2 = bbs[2 * BBd + n1 * 16 + n];
    float bf1   = b_ff1[jh * 16 + n];
    float bf2   = b_ff2[jh * 16 + n];
    float bta   = b_ta [jh * 16 + n];
    float btb   = b_tb [jh * 16 + n];

    for (int e = tid; e < 1024; e += NTHR) g_h[g * 1024 + e] = 0.0f;
    __syncthreads();
    group_barrier(barS, 16);

    float* act0 = smf + FB_OFF_ACT;
    float* act1 = smf + FB_OFF_ACT + FB_SZ_ACTBUF;

    for (int t = 0; t < Ss; t++) {
        if (*(volatile int*)&g_abort) break;
        {
            u64 p0a = 0, p0b = 0, p1a = 0, p1b = 0;
            fb_load_rows32(act0, x + ((size_t)(m1 * 32) * Ss + t) * Ii, Ss * Ii);
            cp_commit();
#pragma unroll
            for (int cix = 0; cix < 6; cix++) {
                float* cur = (cix & 1) ? act1 : act0;
                if (cix < 5) {
                    int cn = cix + 1;
                    float* nxt = (cn & 1) ? act1 : act0;
                    if (cn < 2)
                        fb_load_rows32(nxt, x + ((size_t)(m1 * 32) * Ss + t) * Ii + cn * 128, Ss * Ii);
                    else
                        fb_load_rows32(nxt, g_h + (m1 * 32) * Hh + (cn - 2) * 128, Hh);
                    cp_commit();
                    cp_wait1();
                } else {
                    cp_wait0();
                }
                __syncthreads();
                fb_mac32x16(cur, smf + FB_OFF_W1 + n * FB_P1 + cix * 128, p0a, p0b, p1a, p1b, mg);
                __syncthreads();
            }
            int j = n1 * 16 + n;
            g_zA[(m1 * 32 + mg * 2) * BBd + j]     = tanhf(sum2(p0a) + sum2(p0b) + bz0);
            g_zA[(m1 * 32 + mg * 2 + 1) * BBd + j] = tanhf(sum2(p1a) + sum2(p1b) + bz0);
        }
        group_barrier(barS, 16);
#pragma unroll
        for (int l = 0; l < 3; l++) {
            const float* zin = (l == 1) ? g_zB : g_zA;
            float*       zot = (l == 1) ? g_zA : g_zB;
            u64 p0a = 0, p0b = 0, p1a = 0, p1b = 0;
            fb_load_rows32(act0, zin + (m1 * 32) * BBd, BBd);
            cp_commit();
#pragma unroll
            for (int cix = 0; cix < 2; cix++) {
                if (cix == 0) {
                    fb_load_rows32(act1, zin + (m1 * 32) * BBd + 128, BBd);
                    cp_commit();
                    cp_wait1();
                } else {
                    cp_wait0();
                }
                __syncthreads();
                fb_mac32x16((cix ? act1 : act0), smf + FB_OFF_WB + (l * 16 + n) * FB_PB + cix * 128,
                            p0a, p0b, p1a, p1b, mg);
                __syncthreads();
            }
            int j = n1 * 16 + n;
            float bl = (l == 0) ? bb_l0 : (l == 1) ? bb_l1 : bb_l2;
            zot[(m1 * 32 + mg * 2) * BBd + j]     = tanhf(sum2(p0a) + sum2(p0b) + bl);
            zot[(m1 * 32 + mg * 2 + 1) * BBd + j] = tanhf(sum2(p1a) + sum2(p1b) + bl);
            if (l < 2) group_barrier(barS, 16);
            else       group_barrier(barH, 32);
        }
        {
            u64 acc[4][4];
#pragma unroll
            for (int i = 0; i < 4; i++)
#pragma unroll
                for (int hh = 0; hh < 4; hh++) acc[i][hh] = 0;
            fb_load_rows64(act0, g_zB + (mh * 64) * BBd, BBd);
            cp_commit();
#pragma unroll
            for (int cix = 0; cix < 4; cix++) {
                float* cur = (cix & 1) ? act1 : act0;
                if (cix < 3) {
                    float* nxt = ((cix + 1) & 1) ? act1 : act0;
                    fb_load_rows64(nxt, g_zB + (mh * 64) * BBd + (cix + 1) * 64, BBd);
                    cp_commit();
                    cp_wait1();
                } else {
                    cp_wait0();
                }
                __syncthreads();
                fb_mac_heads(cur, smf + FB_OFF_WH + cix * 64, mg, n, acc);
                __syncthreads();
            }
            int j = jh * 16 + n;
#pragma unroll
            for (int i = 0; i < 4; i++) {
                int b = mh * 64 + mg * 4 + i;
                float tst = ts[(size_t)b * Ss + t];
                float f1  = tanhf(sum2(acc[i][0]) + bf1);
                float f2  = tanhf(sum2(acc[i][1]) + bf2);
                float ta_ = sum2(acc[i][2]) + bta;
                float tb_ = sum2(acc[i][3]) + btb;
                float ti  = 1.0f / (1.0f + expf(-(ta_ * tst + tb_)));
                g_h[b * Hh + j] = f1 + ti * (f2 - f1);
            }
        }
        group_barrier(barH, 32);
    }
    {
        int mo = g >> 2, no = g & 3;
        int m  = mo * 8 + (tid >> 5);
        int nn = no * 32 + (tid & 31);
        float acc = b_out[nn];
        const float* hr = g_h + m * Hh;
#pragma unroll 8
        for (int k = 0; k < Hh; k++) acc += hr[k] * W_out[k * Oo + nn];
        out[m * Oo + nn] = acc;
    }
}

// ============================================================================
extern "C" void kernel_launch(void* const* d_in, const int* in_sizes, int n_in,
                              void* d_out, int out_size) {
    const float* x     = (const float*)d_in[0];
    const float* ts    = (const float*)d_in[1];
    const float* Wb0   = (const float*)d_in[2];
    const float* bb0   = (const float*)d_in[3];
    const float* Wbs   = (const float*)d_in[4];
    const float* bbs   = (const float*)d_in[5];
    const float* W_ff1 = (const float*)d_in[6];
    const float* b_ff1 = (const float*)d_in[7];
    const float* W_ff2 = (const float*)d_in[8];
    const float* b_ff2 = (const float*)d_in[9];
    const float* W_ta  = (const float*)d_in[10];
    const float* b_ta  = (const float*)d_in[11];
    const float* W_tb  = (const float*)d_in[12];
    const float* b_tb  = (const float*)d_in[13];
    const float* W_out = (const float*)d_in[14];
    const float* b_out = (const float*)d_in[15];
    float* outp = (float*)d_out;

    // try cluster path (deterministic capability check every call)
    bool useCluster = false;
    cudaLaunchConfig_t cfg = {};
    cudaLaunchAttribute attrs[1];
    {
        cudaError_t e1 = cudaFuncSetAttribute(lnn_cluster_kernel,
                            cudaFuncAttributeMaxDynamicSharedMemorySize, SMEM_CL_BYTES);
        cudaError_t e2 = cudaFuncSetAttribute(lnn_cluster_kernel,
                            cudaFuncAttributeNonPortableClusterSizeAllowed, 1);
        cfg.gridDim = {NCTA, 1, 1};
        cfg.blockDim = {NTHR, 1, 1};
        cfg.dynamicSmemBytes = SMEM_CL_BYTES;
        cfg.stream = 0;
        attrs[0].id = cudaLaunchAttributeClusterDimension;
        attrs[0].val.clusterDim = {CLSZ, 1, 1};
        cfg.attrs = attrs;
        cfg.numAttrs = 1;
        int numClusters = 0;
        cudaError_t e3 = cudaOccupancyMaxActiveClusters(&numClusters, lnn_cluster_kernel, &cfg);
        useCluster = (e1 == cudaSuccess && e2 == cudaSuccess &&
                      e3 == cudaSuccess && numClusters >= 1);
        if (!useCluster) (void)cudaGetLastError();   // clear sticky error
    }

    if (useCluster) {
        cudaError_t le = cudaLaunchKernelEx(&cfg, lnn_cluster_kernel,
                             x, ts, Wb0, bb0, Wbs, bbs,
                             W_ff1, b_ff1, W_ff2, b_ff2,
                             W_ta, b_ta, W_tb, b_tb,
                             W_out, b_out, outp);
        if (le == cudaSuccess) return;
        (void)cudaGetLastError();                    // clear and fall through
    }

    cudaFuncSetAttribute(lnn_fallback_kernel,
                         cudaFuncAttributeMaxDynamicSharedMemorySize, FB_SMEM_BYTES);
    lnn_fallback_kernel<<<NCTA, NTHR, FB_SMEM_BYTES>>>(x, ts, Wb0, bb0, Wbs, bbs,
                                                       W_ff1, b_ff1, W_ff2, b_ff2,
                                                       W_ta, b_ta, W_tb, b_tb,
                                                       W_out, b_out, outp);
}

// round 8
// speedup vs baseline: 1.6003x; 1.6003x over previous
#include <cuda_runtime.h>
#include <math.h>

#define NCTA 128
#define NTHR 512
#define Bb 256      // batch
#define Ss 512      // seq len
#define Ii 256      // input dim
#define Hh 512      // hidden dim
#define BBd 256     // backbone dim
#define Oo 128      // out dim

// shared memory layout (floats)
#define P1   772    // stage1 weight pitch (768 + 4)
#define PB   260    // backbone/head weight pitch (256 + 4)
#define PA1  132    // act pitch, 32-row chunks (128 + 4)
#define PAH  68     // act pitch, 64-row chunks (64 + 4)

#define OFF_W1  0
#define SZ_W1   (16 * P1)          // 12352
#define OFF_WB  (OFF_W1 + SZ_W1)
#define SZ_WB   (48 * PB)          // 12480
#define OFF_WH  (OFF_WB + SZ_WB)
#define SZ_WH   (64 * PB)          // 16640
#define OFF_ACT (OFF_WH + SZ_WH)
#define SZ_ACTBUF 4352             // max(32*132, 64*68)
#define SZ_ACT  (2 * SZ_ACTBUF)
#define SMEM_FLOATS (OFF_ACT + SZ_ACT)   // 50176
#define SMEM_BYTES  (SMEM_FLOATS * 4)    // 200704

typedef unsigned long long u64;

// ---------------- device scratch ----------
__device__ float g_h[Bb * Hh];
__device__ float g_zA[Bb * BBd];
__device__ float g_zB[Bb * BBd];
__device__ int   g_abort = 0;

struct __align__(128) Bar { unsigned count; unsigned gen; unsigned pad[30]; };
__device__ Bar g_bar16[8];
__device__ Bar g_bar32[4];

// ---------------- group barrier (R4-proven) --------------------------------
__device__ __forceinline__ void group_barrier(Bar* b, unsigned nctas) {
    __syncthreads();
    if (threadIdx.x == 0) {
        if (!*(volatile int*)&g_abort) {
            __threadfence();
            volatile unsigned* vgen = (volatile unsigned*)&b->gen;
            unsigned gen = *vgen;                 // read BEFORE arriving
            unsigned rank = atomicAdd(&b->count, 1);
            if (rank == nctas - 1) {
                atomicExch(&b->count, 0);
                __threadfence();
                atomicAdd((unsigned*)&b->gen, 1);
            } else {
                long long t0 = clock64();
                while (*vgen == gen) {
                    __nanosleep(32);
                    if (*(volatile int*)&g_abort) break;
                    if (clock64() - t0 > 2000000000LL) { atomicExch(&g_abort, 1); break; }
                }
            }
            __threadfence();
        }
    }
    __syncthreads();
}

// ---------------- packed f32x2 FMA -----------------------------------------
__device__ __forceinline__ u64 ffma2(u64 a, u64 b, u64 c) {
    u64 d;
    asm("fma.rn.f32x2 %0, %1, %2, %3;" : "=l"(d) : "l"(a), "l"(b), "l"(c));
    return d;
}
__device__ __forceinline__ float sum2(u64 v) {
    union { u64 u; float2 f; } cv; cv.u = v;
    return cv.f.x + cv.f.y;
}

// ---------------- cp.async ----------------
__device__ __forceinline__ void cp16(float* sdst, const float* gsrc) {
    unsigned saddr = (unsigned)__cvta_generic_to_shared(sdst);
    asm volatile("cp.async.cg.shared.global [%0], [%1], 16;" :: "r"(saddr), "l"(gsrc));
}
__device__ __forceinline__ void cp_commit() { asm volatile("cp.async.commit_group;"); }
__device__ __forceinline__ void cp_wait0()  { asm volatile("cp.async.wait_group 0;"); }
__device__ __forceinline__ void cp_wait1()  { asm volatile("cp.async.wait_group 1;"); }

// load 32 rows x 128 floats (pitch PA1); 1024 cp16 over 512 threads
__device__ __forceinline__ void load_rows32(float* sdst, const float* gbase, int gstride) {
    int tid = threadIdx.x;
#pragma unroll
    for (int i = 0; i < 2; i++) {
        int e = tid + i * NTHR;
        int r = e >> 5, v = e & 31;
        cp16(sdst + r * PA1 + v * 4, gbase + (size_t)r * gstride + v * 4);
    }
}
// load 64 rows x 64 floats (pitch PAH)
__device__ __forceinline__ void load_rows64(float* sdst, const float* gbase, int gstride) {
    int tid = threadIdx.x;
#pragma unroll
    for (int i = 0; i < 2; i++) {
        int e = tid + i * NTHR;
        int r = e >> 4, v = e & 15;
        cp16(sdst + r * PAH + v * 4, gbase + (size_t)r * gstride + v * 4);
    }
}

// 1-row MAC over one staged chunk of 128 k's (2 packed chains)
__device__ __forceinline__ void mac1row(const float* sA, const float* wrow,
                                        u64& p0a, u64& p0b, int mg) {
    const ulonglong2* a0 = (const ulonglong2*)(sA + mg * PA1);
    const ulonglong2* w4 = (const ulonglong2*)wrow;
#pragma unroll
    for (int q = 0; q < 32; q++) {
        ulonglong2 w  = w4[q];
        ulonglong2 x0 = a0[q];
        p0a = ffma2(x0.x, w.x, p0a);
        p0b = ffma2(x0.y, w.y, p0b);
    }
}

// heads: 2 rows x 4 mats over one chunk of 64 k's (8 packed chains)
__device__ __forceinline__ void mac_heads(const float* sA, const float* wbase,
                                          int mgh, int ng, u64 acc[2][4]) {
    const ulonglong2* a0 = (const ulonglong2*)(sA + (mgh * 2 + 0) * PAH);
    const ulonglong2* a1 = (const ulonglong2*)(sA + (mgh * 2 + 1) * PAH);
    const ulonglong2* w0 = (const ulonglong2*)(wbase + (0 * 16 + ng) * PB);
    const ulonglong2* w1 = (const ulonglong2*)(wbase + (1 * 16 + ng) * PB);
    const ulonglong2* w2 = (const ulonglong2*)(wbase + (2 * 16 + ng) * PB);
    const ulonglong2* w3 = (const ulonglong2*)(wbase + (3 * 16 + ng) * PB);
#pragma unroll
    for (int q = 0; q < 16; q++) {
        ulonglong2 wv0 = w0[q], wv1 = w1[q], wv2 = w2[q], wv3 = w3[q];
        ulonglong2 av;
        av = a0[q];
        acc[0][0] = ffma2(av.x, wv0.x, acc[0][0]); acc[0][0] = ffma2(av.y, wv0.y, acc[0][0]);
        acc[0][1] = ffma2(av.x, wv1.x, acc[0][1]); acc[0][1] = ffma2(av.y, wv1.y, acc[0][1]);
        acc[0][2] = ffma2(av.x, wv2.x, acc[0][2]); acc[0][2] = ffma2(av.y, wv2.y, acc[0][2]);
        acc[0][3] = ffma2(av.x, wv3.x, acc[0][3]); acc[0][3] = ffma2(av.y, wv3.y, acc[0][3]);
        av = a1[q];
        acc[1][0] = ffma2(av.x, wv0.x, acc[1][0]); acc[1][0] = ffma2(av.y, wv0.y, acc[1][0]);
        acc[1][1] = ffma2(av.x, wv1.x, acc[1][1]); acc[1][1] = ffma2(av.y, wv1.y, acc[1][1]);
        acc[1][2] = ffma2(av.x, wv2.x, acc[1][2]); acc[1][2] = ffma2(av.y, wv2.y, acc[1][2]);
        acc[1][3] = ffma2(av.x, wv3.x, acc[1][3]); acc[1][3] = ffma2(av.y, wv3.y, acc[1][3]);
    }
}

__global__ void __launch_bounds__(NTHR, 1)
lnn_kernel(const float* __restrict__ x,     const float* __restrict__ ts,
           const float* __restrict__ Wb0,   const float* __restrict__ bb0,
           const float* __restrict__ Wbs,   const float* __restrict__ bbs,
           const float* __restrict__ W_ff1, const float* __restrict__ b_ff1,
           const float* __restrict__ W_ff2, const float* __restrict__ b_ff2,
           const float* __restrict__ W_ta,  const float* __restrict__ b_ta,
           const float* __restrict__ W_tb,  const float* __restrict__ b_tb,
           const float* __restrict__ W_out, const float* __restrict__ b_out,
           float* __restrict__ out) {
    extern __shared__ float smf[];
    const int tid = threadIdx.x;
    const int g   = blockIdx.x;
    const int n   = tid & 15;     // output col within 16-wide slice
    const int mg  = tid >> 4;     // 0..31: stage/backbone row; heads row-pair
    const int m1  = g >> 4;       // 8 M-tiles of 32 rows
    const int n1  = g & 15;       // 16 N-slices
    const int mh  = g >> 5;       // 4 heads M-tiles of 64 rows
    const int jh  = g & 31;       // 32 heads j-slices

    Bar* barS = &g_bar16[m1];
    Bar* barH = &g_bar32[mh];

    if (tid == 0) *(volatile int*)&g_abort = 0;

    // ---- one-time weight loads (transposed, k contiguous) ----
    for (int e = tid; e < 16 * 768; e += NTHR) {
        int nn = e / 768, k = e % 768;
        smf[OFF_W1 + nn * P1 + k] = Wb0[k * BBd + n1 * 16 + nn];
    }
    for (int e = tid; e < 3 * 16 * 256; e += NTHR) {
        int l = e / (16 * 256);
        int rr = e % (16 * 256);
        int nn = rr / 256, k = rr % 256;
        smf[OFF_WB + (l * 16 + nn) * PB + k] = Wbs[(l * BBd + k) * BBd + n1 * 16 + nn];
    }
    for (int e = tid; e < 64 * 256; e += NTHR) {
        int rr = e / 256, k = e % 256;
        int hh = rr / 16, ng = rr % 16;
        const float* Wsrc = (hh == 0) ? W_ff1 : (hh == 1) ? W_ff2 : (hh == 2) ? W_ta : W_tb;
        smf[OFF_WH + rr * PB + k] = Wsrc[k * Hh + jh * 16 + ng];
    }
    // biases
    float bz0   = bb0[n1 * 16 + n];
    float bb_l0 = bbs[0 * BBd + n1 * 16 + n];
    float bb_l1 = bbs[1 * BBd + n1 * 16 + n];
    float bb_l2 = bbs[2 * BBd + n1 * 16 + n];
    float bf1   = b_ff1[jh * 16 + n];
    float bf2   = b_ff2[jh * 16 + n];
    float bta   = b_ta [jh * 16 + n];
    float btb   = b_tb [jh * 16 + n];

    // zero hidden state stripe (deterministic per replay)
    for (int e = tid; e < 1024; e += NTHR) g_h[g * 1024 + e] = 0.0f;
    __syncthreads();
    group_barrier(barS, 16);

    float* act0 = smf + OFF_ACT;
    float* act1 = smf + OFF_ACT + SZ_ACTBUF;

    const int rowS = m1 * 32 + mg;     // this thread's stage/backbone row
    const int jS   = n1 * 16 + n;
    const int jHd  = jh * 16 + n;

    for (int t = 0; t < Ss; t++) {
        if (*(volatile int*)&g_abort) break;

        // ===== stage 1: z0 = tanh([x_t,h] @ Wb0 + bb0) =====
        {
            u64 p0a = 0, p0b = 0;
            load_rows32(act0, x + ((size_t)(m1 * 32) * Ss + t) * Ii, Ss * Ii);
            cp_commit();
#pragma unroll
            for (int c = 0; c < 6; c++) {
                float* cur = (c & 1) ? act1 : act0;
                if (c < 5) {
                    int cn = c + 1;
                    float* nxt = (cn & 1) ? act1 : act0;
                    if (cn < 2)
                        load_rows32(nxt, x + ((size_t)(m1 * 32) * Ss + t) * Ii + cn * 128, Ss * Ii);
                    else
                        load_rows32(nxt, g_h + (m1 * 32) * Hh + (cn - 2) * 128, Hh);
                    cp_commit();
                    cp_wait1();
                } else {
                    cp_wait0();
                }
                __syncthreads();
                mac1row(cur, smf + OFF_W1 + n * P1 + c * 128, p0a, p0b, mg);
                __syncthreads();
            }
            g_zA[rowS * BBd + jS] = tanhf(sum2(p0a) + sum2(p0b) + bz0);
        }
        group_barrier(barS, 16);

        // ===== backbone: 3x z = tanh(z @ Wbs[l] + bbs[l]) =====
#pragma unroll
        for (int l = 0; l < 3; l++) {
            const float* zin = (l == 1) ? g_zB : g_zA;
            float*       zot = (l == 1) ? g_zA : g_zB;
            u64 p0a = 0, p0b = 0;
            load_rows32(act0, zin + (m1 * 32) * BBd, BBd);
            cp_commit();
#pragma unroll
            for (int c = 0; c < 2; c++) {
                if (c == 0) {
                    load_rows32(act1, zin + (m1 * 32) * BBd + 128, BBd);
                    cp_commit();
                    cp_wait1();
                } else {
                    cp_wait0();
                }
                __syncthreads();
                mac1row((c ? act1 : act0), smf + OFF_WB + (l * 16 + n) * PB + c * 128,
                        p0a, p0b, mg);
                __syncthreads();
            }
            float bl = (l == 0) ? bb_l0 : (l == 1) ? bb_l1 : bb_l2;
            zot[rowS * BBd + jS] = tanhf(sum2(p0a) + sum2(p0b) + bl);
            if (l < 2) group_barrier(barS, 16);
            else       group_barrier(barH, 32);
        }

        // ===== heads: ff1/ff2/ta/tb + gate -> new h =====
        {
            u64 acc[2][4];
#pragma unroll
            for (int i = 0; i < 2; i++)
#pragma unroll
                for (int hh = 0; hh < 4; hh++) acc[i][hh] = 0;

            load_rows64(act0, g_zB + (mh * 64) * BBd, BBd);
            cp_commit();
#pragma unroll
            for (int c = 0; c < 4; c++) {
                float* cur = (c & 1) ? act1 : act0;
                if (c < 3) {
                    float* nxt = ((c + 1) & 1) ? act1 : act0;
                    load_rows64(nxt, g_zB + (mh * 64) * BBd + (c + 1) * 64, BBd);
                    cp_commit();
                    cp_wait1();
                } else {
                    cp_wait0();
                }
                __syncthreads();
                mac_heads(cur, smf + OFF_WH + c * 64, mg, n, acc);
                __syncthreads();
            }
#pragma unroll
            for (int i = 0; i < 2; i++) {
                int b = mh * 64 + mg * 2 + i;
                float tst = ts[(size_t)b * Ss + t];
                float f1  = tanhf(sum2(acc[i][0]) + bf1);
                float f2  = tanhf(sum2(acc[i][1]) + bf2);
                float ta_ = sum2(acc[i][2]) + bta;
                float tb_ = sum2(acc[i][3]) + btb;
                float ti  = 1.0f / (1.0f + expf(-(ta_ * tst + tb_)));
                g_h[b * Hh + jHd] = f1 + ti * (f2 - f1);
            }
        }
        group_barrier(barH, 32);
    }

    // ===== final: out = h_last @ W_out + b_out =====
    if (tid < 256) {
        int mo = g >> 2, no = g & 3;
        int m  = mo * 8 + (tid >> 5);
        int nn = no * 32 + (tid & 31);
        float acc = b_out[nn];
        const float* hr = g_h + m * Hh;
#pragma unroll 8
        for (int k = 0; k < Hh; k++) acc += hr[k] * W_out[k * Oo + nn];
        out[m * Oo + nn] = acc;
    }
}

extern "C" void kernel_launch(void* const* d_in, const int* in_sizes, int n_in,
                              void* d_out, int out_size) {
    const float* x     = (const float*)d_in[0];
    const float* ts    = (const float*)d_in[1];
    const float* Wb0   = (const float*)d_in[2];
    const float* bb0   = (const float*)d_in[3];
    const float* Wbs   = (const float*)d_in[4];
    const float* bbs   = (const float*)d_in[5];
    const float* W_ff1 = (const float*)d_in[6];
    const float* b_ff1 = (const float*)d_in[7];
    const float* W_ff2 = (const float*)d_in[8];
    const float* b_ff2 = (const float*)d_in[9];
    const float* W_ta  = (const float*)d_in[10];
    const float* b_ta  = (const float*)d_in[11];
    const float* W_tb  = (const float*)d_in[12];
    const float* b_tb  = (const float*)d_in[13];
    const float* W_out = (const float*)d_in[14];
    const float* b_out = (const float*)d_in[15];

    cudaFuncSetAttribute(lnn_kernel, cudaFuncAttributeMaxDynamicSharedMemorySize, SMEM_BYTES);
    lnn_kernel<<<NCTA, NTHR, SMEM_BYTES>>>(x, ts, Wb0, bb0, Wbs, bbs,
                                           W_ff1, b_ff1, W_ff2, b_ff2,
                                           W_ta, b_ta, W_tb, b_tb,
                                           W_out, b_out, (float*)d_out);
}

// round 11
// speedup vs baseline: 2.0955x; 1.3095x over previous
#include <cuda_runtime.h>
#include <math.h>

#define NCTA 128
#define NTHR 256
#define Bb 256
#define Ss 512
#define Ii 256
#define Hh 512
#define BBd 256
#define Oo 128

// shared memory layout (floats)
#define P1   772
#define PB   260
#define PA1  132
#define PAH  68

#define OFF_W1  0
#define SZ_W1   (16 * P1)          // 12352
#define OFF_WB  (OFF_W1 + SZ_W1)
#define SZ_WB   (48 * PB)          // 12480
#define OFF_WH  (OFF_WB + SZ_WB)
#define SZ_WH   (64 * PB)          // 16640
#define OFF_ACT (OFF_WH + SZ_WH)
#define SZ_ACTBUF 4352
#define SMEM_FLOATS (OFF_ACT + 3 * SZ_ACTBUF)   // 54528
#define SMEM_BYTES  (SMEM_FLOATS * 4)           // 218112

typedef unsigned long long u64;

// ---------------- device scratch ----------
__device__ float g_h[Bb * Hh];
__device__ float g_zA[Bb * BBd];
__device__ float g_zB[Bb * BBd];
__device__ int   g_abort = 0;

struct __align__(128) Bar { unsigned count; unsigned gen; unsigned pad[30]; };
__device__ Bar g_bar16[8];
__device__ Bar g_bar32[4];

// ---------------- group barrier (proven in R3/R4/R8; always arrives) -------
__device__ __forceinline__ void group_barrier(Bar* b, unsigned nctas) {
    __syncthreads();
    if (threadIdx.x == 0) {
        __threadfence();
        volatile unsigned* vgen = (volatile unsigned*)&b->gen;
        unsigned gen = *vgen;                 // read BEFORE arriving
        unsigned rank = atomicAdd(&b->count, 1);
        if (rank == nctas - 1) {
            atomicExch(&b->count, 0);
            __threadfence();
            atomicAdd((unsigned*)&b->gen, 1);
        } else {
            long long t0 = clock64();
            while (*vgen == gen) {
                __nanosleep(32);
                if (*(volatile int*)&g_abort) break;
                if (clock64() - t0 > 2000000000LL) { atomicExch(&g_abort, 1); break; }
            }
        }
        __threadfence();
    }
    __syncthreads();
}

// ---------------- packed f32x2 FMA -----------------------------------------
__device__ __forceinline__ u64 ffma2(u64 a, u64 b, u64 c) {
    u64 d;
    asm("fma.rn.f32x2 %0, %1, %2, %3;" : "=l"(d) : "l"(a), "l"(b), "l"(c));
    return d;
}
__device__ __forceinline__ float sum2(u64 v) {
    union { u64 u; float2 f; } cv; cv.u = v;
    return cv.f.x + cv.f.y;
}

// ---------------- cp.async ----------------
__device__ __forceinline__ void cp16(float* sdst, const float* gsrc) {
    unsigned saddr = (unsigned)__cvta_generic_to_shared(sdst);
    asm volatile("cp.async.cg.shared.global [%0], [%1], 16;" :: "r"(saddr), "l"(gsrc));
}
__device__ __forceinline__ void cp_commit() { asm volatile("cp.async.commit_group;"); }
__device__ __forceinline__ void cp_wait0()  { asm volatile("cp.async.wait_group 0;"); }
__device__ __forceinline__ void cp_wait1()  { asm volatile("cp.async.wait_group 1;"); }

__device__ __forceinline__ void load_rows32(float* sdst, const float* gbase, int gstride) {
    int tid = threadIdx.x;
#pragma unroll
    for (int i = 0; i < 4; i++) {
        int e = tid + i * 256;
        int r = e >> 5, v = e & 31;
        cp16(sdst + r * PA1 + v * 4, gbase + (size_t)r * gstride + v * 4);
    }
}
__device__ __forceinline__ void load_rows64(float* sdst, const float* gbase, int gstride) {
    int tid = threadIdx.x;
#pragma unroll
    for (int i = 0; i < 4; i++) {
        int e = tid + i * 256;
        int r = e >> 4, v = e & 15;
        cp16(sdst + r * PAH + v * 4, gbase + (size_t)r * gstride + v * 4);
    }
}

// 32x16 tile MAC over one 128-K chunk (2 rows/thread, 4 packed chains)
__device__ __forceinline__ void mac32x16(const float* sA, const float* wrow,
                                         u64& p0a, u64& p0b, u64& p1a, u64& p1b, int mg) {
    const ulonglong2* a0 = (const ulonglong2*)(sA + (mg * 2) * PA1);
    const ulonglong2* a1 = (const ulonglong2*)(sA + (mg * 2 + 1) * PA1);
    const ulonglong2* w4 = (const ulonglong2*)wrow;
#pragma unroll
    for (int q = 0; q < 32; q++) {
        ulonglong2 w  = w4[q];
        ulonglong2 x0 = a0[q];
        ulonglong2 x1 = a1[q];
        p0a = ffma2(x0.x, w.x, p0a);
        p0b = ffma2(x0.y, w.y, p0b);
        p1a = ffma2(x1.x, w.x, p1a);
        p1b = ffma2(x1.y, w.y, p1b);
    }
}

// heads: 4 rows x 4 mats over one 64-K chunk (16 packed chains)
__device__ __forceinline__ void mac_heads(const float* sA, const float* wbase,
                                          int mg, int ng, u64 acc[4][4]) {
    const ulonglong2* a0 = (const ulonglong2*)(sA + (mg * 4 + 0) * PAH);
    const ulonglong2* a1 = (const ulonglong2*)(sA + (mg * 4 + 1) * PAH);
    const ulonglong2* a2 = (const ulonglong2*)(sA + (mg * 4 + 2) * PAH);
    const ulonglong2* a3 = (const ulonglong2*)(sA + (mg * 4 + 3) * PAH);
    const ulonglong2* w0 = (const ulonglong2*)(wbase + (0 * 16 + ng) * PB);
    const ulonglong2* w1 = (const ulonglong2*)(wbase + (1 * 16 + ng) * PB);
    const ulonglong2* w2 = (const ulonglong2*)(wbase + (2 * 16 + ng) * PB);
    const ulonglong2* w3 = (const ulonglong2*)(wbase + (3 * 16 + ng) * PB);
#pragma unroll
    for (int q = 0; q < 16; q++) {
        ulonglong2 wv0 = w0[q], wv1 = w1[q], wv2 = w2[q], wv3 = w3[q];
        ulonglong2 av;
        av = a0[q];
        acc[0][0] = ffma2(av.x, wv0.x, acc[0][0]); acc[0][0] = ffma2(av.y, wv0.y, acc[0][0]);
        acc[0][1] = ffma2(av.x, wv1.x, acc[0][1]); acc[0][1] = ffma2(av.y, wv1.y, acc[0][1]);
        acc[0][2] = ffma2(av.x, wv2.x, acc[0][2]); acc[0][2] = ffma2(av.y, wv2.y, acc[0][2]);
        acc[0][3] = ffma2(av.x, wv3.x, acc[0][3]); acc[0][3] = ffma2(av.y, wv3.y, acc[0][3]);
        av = a1[q];
        acc[1][0] = ffma2(av.x, wv0.x, acc[1][0]); acc[1][0] = ffma2(av.y, wv0.y, acc[1][0]);
        acc[1][1] = ffma2(av.x, wv1.x, acc[1][1]); acc[1][1] = ffma2(av.y, wv1.y, acc[1][1]);
        acc[1][2] = ffma2(av.x, wv2.x, acc[1][2]); acc[1][2] = ffma2(av.y, wv2.y, acc[1][2]);
        acc[1][3] = ffma2(av.x, wv3.x, acc[1][3]); acc[1][3] = ffma2(av.y, wv3.y, acc[1][3]);
        av = a2[q];
        acc[2][0] = ffma2(av.x, wv0.x, acc[2][0]); acc[2][0] = ffma2(av.y, wv0.y, acc[2][0]);
        acc[2][1] = ffma2(av.x, wv1.x, acc[2][1]); acc[2][1] = ffma2(av.y, wv1.y, acc[2][1]);
        acc[2][2] = ffma2(av.x, wv2.x, acc[2][2]); acc[2][2] = ffma2(av.y, wv2.y, acc[2][2]);
        acc[2][3] = ffma2(av.x, wv3.x, acc[2][3]); acc[2][3] = ffma2(av.y, wv3.y, acc[2][3]);
        av = a3[q];
        acc[3][0] = ffma2(av.x, wv0.x, acc[3][0]); acc[3][0] = ffma2(av.y, wv0.y, acc[3][0]);
        acc[3][1] = ffma2(av.x, wv1.x, acc[3][1]); acc[3][1] = ffma2(av.y, wv1.y, acc[3][1]);
        acc[3][2] = ffma2(av.x, wv2.x, acc[3][2]); acc[3][2] = ffma2(av.y, wv2.y, acc[3][2]);
        acc[3][3] = ffma2(av.x, wv3.x, acc[3][3]); acc[3][3] = ffma2(av.y, wv3.y, acc[3][3]);
    }
}

__global__ void __launch_bounds__(NTHR, 1)
lnn_kernel(const float* __restrict__ x,     const float* __restrict__ ts,
           const float* __restrict__ Wb0,   const float* __restrict__ bb0,
           const float* __restrict__ Wbs,   const float* __restrict__ bbs,
           const float* __restrict__ W_ff1, const float* __restrict__ b_ff1,
           const float* __restrict__ W_ff2, const float* __restrict__ b_ff2,
           const float* __restrict__ W_ta,  const float* __restrict__ b_ta,
           const float* __restrict__ W_tb,  const float* __restrict__ b_tb,
           const float* __restrict__ W_out, const float* __restrict__ b_out,
           float* __restrict__ out) {
    extern __shared__ float smf[];
    const int tid = threadIdx.x;
    const int g   = blockIdx.x;
    const int n   = tid & 15;
    const int mg  = tid >> 4;     // 0..15
    const int m1  = g >> 4;
    const int n1  = g & 15;
    const int mh  = g >> 5;
    const int jh  = g & 31;

    Bar* barS = &g_bar16[m1];
    Bar* barH = &g_bar32[mh];

    if (tid == 0) *(volatile int*)&g_abort = 0;

    // ---- one-time weight loads (transposed, k contiguous) ----
    for (int e = tid; e < 16 * 768; e += NTHR) {
        int nn = e / 768, k = e % 768;
        smf[OFF_W1 + nn * P1 + k] = Wb0[k * BBd + n1 * 16 + nn];
    }
    for (int e = tid; e < 3 * 16 * 256; e += NTHR) {
        int l = e / (16 * 256);
        int rr = e % (16 * 256);
        int nn = rr / 256, k = rr % 256;
        smf[OFF_WB + (l * 16 + nn) * PB + k] = Wbs[(l * BBd + k) * BBd + n1 * 16 + nn];
    }
    for (int e = tid; e < 64 * 256; e += NTHR) {
        int rr = e / 256, k = e % 256;
        int hh = rr / 16, ng = rr % 16;
        const float* Wsrc = (hh == 0) ? W_ff1 : (hh == 1) ? W_ff2 : (hh == 2) ? W_ta : W_tb;
        smf[OFF_WH + rr * PB + k] = Wsrc[k * Hh + jh * 16 + ng];
    }
    float bz0   = bb0[n1 * 16 + n];
    float bb_l0 = bbs[0 * BBd + n1 * 16 + n];
    float bb_l1 = bbs[1 * BBd + n1 * 16 + n];
    float bb_l2 = bbs[2 * BBd + n1 * 16 + n];
    float bf1   = b_ff1[jh * 16 + n];
    float bf2   = b_ff2[jh * 16 + n];
    float bta   = b_ta [jh * 16 + n];
    float btb   = b_tb [jh * 16 + n];

    // zero h stripe (deterministic per replay)
    for (int e = tid; e < 1024; e += NTHR) g_h[g * 1024 + e] = 0.0f;
    __syncthreads();
    group_barrier(barH, 32);

    float* B0 = smf + OFF_ACT;
    float* B1 = B0 + SZ_ACTBUF;
    float* B2 = B1 + SZ_ACTBUF;

    const int rowPair = m1 * 32 + mg * 2;
    const int jS  = n1 * 16 + n;
    const int jHd = jh * 16 + n;
    const float* w1base = smf + OFF_W1 + n * P1;

    // stage1 accumulators carry across barriers (x-part precomputed)
    u64 p0a = 0, p0b = 0, p1a = 0, p1b = 0;
    {   // x-part for t = 0
        const float* xrb = x + ((size_t)(m1 * 32) * Ss + 0) * Ii;
        load_rows32(B0, xrb,       Ss * Ii); cp_commit();
        load_rows32(B1, xrb + 128, Ss * Ii); cp_commit();
        cp_wait1(); __syncthreads(); mac32x16(B0, w1base + 0,   p0a, p0b, p1a, p1b, mg);
        cp_wait0(); __syncthreads(); mac32x16(B1, w1base + 128, p0a, p0b, p1a, p1b, mg);
    }

    for (int t = 0; t < Ss; t++) {
        if (*(volatile int*)&g_abort) break;

        // ===== stage 1 h-part (h(t) sealed by barH of prev step) =====
        {
            const float* hb = g_h + (size_t)(m1 * 32) * Hh;
            load_rows32(B0, hb,       Hh); cp_commit();
            load_rows32(B1, hb + 128, Hh); cp_commit();
            // c0: B0 ready
            cp_wait1(); __syncthreads();
            load_rows32(B2, hb + 256, Hh); cp_commit();
            mac32x16(B0, w1base + 256, p0a, p0b, p1a, p1b, mg);
            // c1: B1 ready
            cp_wait1(); __syncthreads();
            load_rows32(B0, hb + 384, Hh); cp_commit();
            mac32x16(B1, w1base + 384, p0a, p0b, p1a, p1b, mg);
            // c2: B2 ready
            cp_wait1(); __syncthreads();
            mac32x16(B2, w1base + 512, p0a, p0b, p1a, p1b, mg);
            // c3: B0 ready
            cp_wait0(); __syncthreads();
            mac32x16(B0, w1base + 640, p0a, p0b, p1a, p1b, mg);

            g_zA[rowPair * BBd + jS]       = tanhf(sum2(p0a) + sum2(p0b) + bz0);
            g_zA[(rowPair + 1) * BBd + jS] = tanhf(sum2(p1a) + sum2(p1b) + bz0);
        }
        group_barrier(barS, 16);

        // ===== backbone x3 =====
#pragma unroll
        for (int l = 0; l < 3; l++) {
            const float* zin = (l == 1) ? g_zB : g_zA;
            float*       zot = (l == 1) ? g_zA : g_zB;
            u64 q0a = 0, q0b = 0, q1a = 0, q1b = 0;
            const float* zb = zin + (size_t)(m1 * 32) * BBd;
            load_rows32(B0, zb,       BBd); cp_commit();
            load_rows32(B1, zb + 128, BBd); cp_commit();
            const float* wb = smf + OFF_WB + (l * 16 + n) * PB;
            cp_wait1(); __syncthreads(); mac32x16(B0, wb,       q0a, q0b, q1a, q1b, mg);
            cp_wait0(); __syncthreads(); mac32x16(B1, wb + 128, q0a, q0b, q1a, q1b, mg);
            float bl = (l == 0) ? bb_l0 : (l == 1) ? bb_l1 : bb_l2;
            zot[rowPair * BBd + jS]       = tanhf(sum2(q0a) + sum2(q0b) + bl);
            zot[(rowPair + 1) * BBd + jS] = tanhf(sum2(q1a) + sum2(q1b) + bl);
            if (l < 2) group_barrier(barS, 16);
            else       group_barrier(barH, 32);
        }

        // ===== heads: ff1/ff2/ta/tb + gate -> new h =====
        {
            u64 acc[4][4];
#pragma unroll
            for (int i = 0; i < 4; i++)
#pragma unroll
                for (int hh = 0; hh < 4; hh++) acc[i][hh] = 0;

            const float* zb = g_zB + (size_t)(mh * 64) * BBd;
            load_rows64(B0, zb,       BBd); cp_commit();
            load_rows64(B1, zb + 64,  BBd); cp_commit();
            // c0
            cp_wait1(); __syncthreads();
            load_rows64(B2, zb + 128, BBd); cp_commit();
            mac_heads(B0, smf + OFF_WH + 0 * 64, mg, n, acc);
            // c1
            cp_wait1(); __syncthreads();
            load_rows64(B0, zb + 192, BBd); cp_commit();
            mac_heads(B1, smf + OFF_WH + 1 * 64, mg, n, acc);
            // c2
            cp_wait1(); __syncthreads();
            mac_heads(B2, smf + OFF_WH + 2 * 64, mg, n, acc);
            // c3
            cp_wait0(); __syncthreads();
            mac_heads(B0, smf + OFF_WH + 3 * 64, mg, n, acc);

#pragma unroll
            for (int i = 0; i < 4; i++) {
                int b = mh * 64 + mg * 4 + i;
                float tst = ts[(size_t)b * Ss + t];
                float f1  = tanhf(sum2(acc[i][0]) + bf1);
                float f2  = tanhf(sum2(acc[i][1]) + bf2);
                float ta_ = sum2(acc[i][2]) + bta;
                float tb_ = sum2(acc[i][3]) + btb;
                float ti  = 1.0f / (1.0f + __expf(-(ta_ * tst + tb_)));
                g_h[b * Hh + jHd] = f1 + ti * (f2 - f1);
            }
        }
        group_barrier(barH, 32);

        // ===== overlap: x-part of stage1 for t+1 (no h dependency) =====
        p0a = 0; p0b = 0; p1a = 0; p1b = 0;
        if (t + 1 < Ss) {
            const float* xrb = x + ((size_t)(m1 * 32) * Ss + (t + 1)) * Ii;
            load_rows32(B0, xrb,       Ss * Ii); cp_commit();
            load_rows32(B1, xrb + 128, Ss * Ii); cp_commit();
            cp_wait1(); __syncthreads(); mac32x16(B0, w1base + 0,   p0a, p0b, p1a, p1b, mg);
            cp_wait0(); __syncthreads(); mac32x16(B1, w1base + 128, p0a, p0b, p1a, p1b, mg);
        }
    }

    // ===== final: out = h_last @ W_out + b_out =====
    {
        int mo = g >> 2, no = g & 3;
        int m  = mo * 8 + (tid >> 5);
        int nn = no * 32 + (tid & 31);
        float acc = b_out[nn];
        const float* hr = g_h + (size_t)m * Hh;
#pragma unroll 8
        for (int k = 0; k < Hh; k++) acc += hr[k] * W_out[k * Oo + nn];
        out[m * Oo + nn] = acc;
    }
}

extern "C" void kernel_launch(void* const* d_in, const int* in_sizes, int n_in,
                              void* d_out, int out_size) {
    const float* x     = (const float*)d_in[0];
    const float* ts    = (const float*)d_in[1];
    const float* Wb0   = (const float*)d_in[2];
    const float* bb0   = (const float*)d_in[3];
    const float* Wbs   = (const float*)d_in[4];
    const float* bbs   = (const float*)d_in[5];
    const float* W_ff1 = (const float*)d_in[6];
    const float* b_ff1 = (const float*)d_in[7];
    const float* W_ff2 = (const float*)d_in[8];
    const float* b_ff2 = (const float*)d_in[9];
    const float* W_ta  = (const float*)d_in[10];
    const float* b_ta  = (const float*)d_in[11];
    const float* W_tb  = (const float*)d_in[12];
    const float* b_tb  = (const float*)d_in[13];
    const float* W_out = (const float*)d_in[14];
    const float* b_out = (const float*)d_in[15];

    cudaFuncSetAttribute(lnn_kernel, cudaFuncAttributeMaxDynamicSharedMemorySize, SMEM_BYTES);
    lnn_kernel<<<NCTA, NTHR, SMEM_BYTES>>>(x, ts, Wb0, bb0, Wbs, bbs,
                                           W_ff1, b_ff1, W_ff2, b_ff2,
                                           W_ta, b_ta, W_tb, b_tb,
                                           W_out, b_out, (float*)d_out);
}